// round 2
// baseline (speedup 1.0000x reference)
#include <cuda_runtime.h>
#include <math.h>

#define N_NODES 30000
#define DIM     128
#define T_LINKS 3000
#define K_NEG   75
#define NQ      (2 * T_LINKS)
#define EPSF    1e-7f
#define MAXSQ   50.0f
#define GAMMA   1.0f

// ---------------- scratch (no allocations allowed) ----------------
__device__ int   g_is64;
__device__ float g_contrib[NQ];

// ---------------- kernel 0: detect link dtype (int64 vs int32) ----------------
// jax requests int64 but silently produces int32 without x64 enabled. Detect
// device-side: read the first 6000 int32 words (in-bounds under either dtype).
// int64-LE with values < 30000 => every odd word is 0. A misdetect would need
// an int32 buffer whose 3000 odd-position values are ALL zero.
__global__ void detect_kernel(const int* __restrict__ w) {
    __shared__ int nz;
    if (threadIdx.x == 0) nz = 0;
    __syncthreads();
    int loc = 0;
    for (int i = threadIdx.x; i < 3000; i += blockDim.x)
        if (w[2 * i + 1] != 0) loc = 1;
    if (loc) atomicOr(&nz, 1);
    __syncthreads();
    if (threadIdx.x == 0) g_is64 = (nz == 0) ? 1 : 0;
}

// ---------------- kernel 1: one warp per query ----------------
// sq(prod) = min(K*acosh(max(-prod*c, 1+eps))^2, 50) is weakly monotone
// non-decreasing in (-prod), so the 75 smallest distances are the mapped 75
// largest prods. With emb ~ N(0,1), P(prod >= -(1+eps)K) ~ 0.53, so the 75
// nearest all clip to theta = 1+eps and sq = sq_min exactly; the row
// contribution collapses to 75 * relu(D - sq_min). We count clipped
// candidates with early exit (~144 scanned per row). Generic lexicographic
// top-75 fallback guarantees correctness if count < 75 (won't trigger here).
__global__ void __launch_bounds__(256, 8)
main_kernel(const float* __restrict__ emb,
            const float* __restrict__ cptr,
            const void*  __restrict__ links) {
    const int gwarp = (blockIdx.x * blockDim.x + threadIdx.x) >> 5;
    const int lane  = threadIdx.x & 31;
    if (gwarp >= NQ) return;

    const int li   = gwarp % T_LINKS;   // link index
    const int side = gwarp / T_LINKS;   // 0 = left query, 1 = right query

    long l, r;
    if (g_is64) {
        const long long* p = (const long long*)links;
        l = (long)p[2 * li]; r = (long)p[2 * li + 1];
    } else {
        const int* p = (const int*)links;
        l = p[2 * li]; r = p[2 * li + 1];
    }

    const float c  = cptr[0];
    const float K  = 1.0f / c;
    const float thr_theta = 1.0f + EPSF;          // rounds to 1+2^-23, same as jax fp32
    const float prod_thr  = -thr_theta * K;       // clipped  <=>  prod >= prod_thr
    float acm = acoshf(thr_theta);
    const float sq_min = fminf(K * acm * acm, MAXSQ);

    const float4* E4 = (const float4*)emb;

    // ---- D = sqdist(left, right) + GAMMA ----
    float4 lv = E4[(size_t)l * (DIM / 4) + lane];
    float4 rv = E4[(size_t)r * (DIM / 4) + lane];
    float pd = lv.x * rv.x + lv.y * rv.y + lv.z * rv.z + lv.w * rv.w;
    if (lane == 0) pd -= 2.0f * lv.x * rv.x;      // Minkowski: -x0*y0
    #pragma unroll
    for (int o = 16; o; o >>= 1) pd += __shfl_xor_sync(0xffffffffu, pd, o);
    float th = fmaxf(-pd * c, thr_theta);
    float ac = acoshf(th);
    float D  = fminf(K * ac * ac, MAXSQ) + GAMMA;

    // ---- query vector (negate dim 0 so plain dot == Minkowski dot) ----
    const long qrow = (side == 0) ? l : r;
    float4 qv = E4[(size_t)qrow * (DIM / 4) + lane];
    if (lane == 0) qv.x = -qv.x;

    // ---- early-exit clipped-candidate count, 4 candidates / iter for ILP ----
    int count = 0;
    bool reached = false;
    for (int c0 = 0; c0 < N_NODES; c0 += 4) {
        float4 e0 = E4[(size_t)(c0 + 0) * (DIM / 4) + lane];
        float4 e1 = E4[(size_t)(c0 + 1) * (DIM / 4) + lane];
        float4 e2 = E4[(size_t)(c0 + 2) * (DIM / 4) + lane];
        float4 e3 = E4[(size_t)(c0 + 3) * (DIM / 4) + lane];
        float p0 = qv.x * e0.x + qv.y * e0.y + qv.z * e0.z + qv.w * e0.w;
        float p1 = qv.x * e1.x + qv.y * e1.y + qv.z * e1.z + qv.w * e1.w;
        float p2 = qv.x * e2.x + qv.y * e2.y + qv.z * e2.z + qv.w * e2.w;
        float p3 = qv.x * e3.x + qv.y * e3.y + qv.z * e3.z + qv.w * e3.w;
        #pragma unroll
        for (int o = 16; o; o >>= 1) {
            p0 += __shfl_xor_sync(0xffffffffu, p0, o);
            p1 += __shfl_xor_sync(0xffffffffu, p1, o);
            p2 += __shfl_xor_sync(0xffffffffu, p2, o);
            p3 += __shfl_xor_sync(0xffffffffu, p3, o);
        }
        count += (p0 >= prod_thr) + (p1 >= prod_thr)
               + (p2 >= prod_thr) + (p3 >= prod_thr);
        if (count >= K_NEG) { reached = true; break; }
    }

    float contrib;
    if (reached) {
        contrib = (float)K_NEG * fmaxf(D - sq_min, 0.0f);
    } else {
        // ---- generic fallback: top-75 largest (prod, -idx), lexicographic ----
        const float* q = emb + (size_t)qrow * DIM;
        float prevP = INFINITY; int prevI = -1;
        float s = 0.0f;
        for (int pick = 0; pick < K_NEG; ++pick) {
            float bp = -INFINITY; int bi = 0x7fffffff;
            for (int j = lane; j < N_NODES; j += 32) {
                const float* e = emb + (size_t)j * DIM;
                float p = -q[0] * e[0];
                #pragma unroll 8
                for (int d = 1; d < DIM; ++d) p += q[d] * e[d];
                bool after = (p < prevP) || (p == prevP && j > prevI);
                if (after && (p > bp || (p == bp && j < bi))) { bp = p; bi = j; }
            }
            #pragma unroll
            for (int o = 16; o; o >>= 1) {
                float op = __shfl_xor_sync(0xffffffffu, bp, o);
                int   oi = __shfl_xor_sync(0xffffffffu, bi, o);
                if (op > bp || (op == bp && oi < bi)) { bp = op; bi = oi; }
            }
            prevP = bp; prevI = bi;
            float t2 = fmaxf(-bp * c, thr_theta);
            float a2 = acoshf(t2);
            float sq = fminf(K * a2 * a2, MAXSQ);
            s += fmaxf(D - sq, 0.0f);
        }
        contrib = s;
    }

    if (lane == 0) g_contrib[gwarp] = contrib;
}

// ---------------- kernel 2: deterministic reduction ----------------
__global__ void reduce_kernel(float* __restrict__ out) {
    __shared__ float sm[256];
    float s = 0.0f;
    for (int i = threadIdx.x; i < NQ; i += 256) s += g_contrib[i];
    sm[threadIdx.x] = s;
    __syncthreads();
    #pragma unroll
    for (int o = 128; o; o >>= 1) {
        if (threadIdx.x < o) sm[threadIdx.x] += sm[threadIdx.x + o];
        __syncthreads();
    }
    if (threadIdx.x == 0)
        out[0] = sm[0] / (2.0f * (float)K_NEG * (float)T_LINKS);
}

extern "C" void kernel_launch(void* const* d_in, const int* in_sizes, int n_in,
                              void* d_out, int out_size) {
    const float* emb   = (const float*)d_in[0];
    const float* cptr  = (const float*)d_in[1];
    const void*  links = d_in[2];

    detect_kernel<<<1, 256>>>((const int*)links);

    const int warps_per_block = 256 / 32;
    const int blocks = (NQ + warps_per_block - 1) / warps_per_block;
    main_kernel<<<blocks, 256>>>(emb, cptr, links);

    reduce_kernel<<<1, 256>>>((float*)d_out);
}

// round 3
// speedup vs baseline: 1.0312x; 1.0312x over previous
#include <cuda_runtime.h>
#include <math.h>

#define N_NODES 30000
#define DIM     128
#define T_LINKS 3000
#define K_NEG   75
#define NQ      (2 * T_LINKS)
#define EPSF    1e-7f
#define MAXSQ   50.0f
#define GAMMA   1.0f

#define WARPS_PER_BLOCK 8
#define NB (NQ / WARPS_PER_BLOCK)        // 750 blocks, 1 warp = 1 query
#define TILE 32                           // candidates per smem tile
#define NT ((N_NODES + TILE - 1) / TILE)  // 938 tiles
#define ROWF 132                          // padded row stride in floats (+16B)

// ---------------- scratch (no device allocations allowed) ----------------
__device__ float        g_partial[NB];
__device__ unsigned int g_ticket = 0;

// Single fused kernel:
//   per-block link-dtype detection -> per-warp query staging -> block-shared
//   candidate tiles with lane-per-candidate dot products (no shuffles) ->
//   early exit when all 8 queries reached 75 clipped candidates ->
//   last-block deterministic reduction.
//
// Math: sq(prod) = min(K*acosh(max(-prod*c, 1+eps))^2, 50) is weakly monotone
// non-decreasing in (-prod). With emb ~ N(0,1), >half of all candidates clip
// to theta = 1+eps (the global minimum sq_min), so the 75 smallest distances
// are ALL exactly sq_min and the row contribution is 75*relu(D - sq_min).
// We count clipped candidates with early exit; a generic lexicographic
// top-75 fallback guarantees correctness if a query has fewer than 75
// clipped candidates (never triggers on this data).
__global__ void __launch_bounds__(256)
fused_kernel(const float* __restrict__ emb,
             const float* __restrict__ cptr,
             const void*  __restrict__ links,
             float* __restrict__ out) {
    __shared__ float s_cand[TILE][ROWF];           // 16896 B
    __shared__ float s_q[WARPS_PER_BLOCK][DIM];    //  4096 B
    __shared__ float s_wsum[WARPS_PER_BLOCK];
    __shared__ int   s_islast;

    const int t    = threadIdx.x;
    const int wid  = t >> 5;
    const int lane = t & 31;
    const int bid  = blockIdx.x;

    // ---- link dtype detection (block-local, reads 12KB from L2) ----
    // int64-LE links with values < 30000 => all odd 32-bit words are zero.
    int loc = 0;
    {
        const int* w = (const int*)links;
        for (int i = t; i < T_LINKS; i += 256)
            if (w[2 * i + 1] != 0) loc = 1;
    }
    const int is64 = !__syncthreads_or(loc);

    // ---- per-warp query setup ----
    const int gwarp = bid * WARPS_PER_BLOCK + wid;
    const int li    = gwarp % T_LINKS;
    const int side  = gwarp / T_LINKS;        // 0 = left query, 1 = right

    int l, r;
    if (is64) {
        const long long* p = (const long long*)links;
        l = (int)p[2 * li]; r = (int)p[2 * li + 1];
    } else {
        const int* p = (const int*)links;
        l = p[2 * li]; r = p[2 * li + 1];
    }

    const float c  = cptr[0];
    const float K  = 1.0f / c;
    const float thr_theta = 1.0f + EPSF;       // rounds to 1+2^-23, same as jax fp32
    const float prod_thr  = -thr_theta * K;    // clipped  <=>  prod >= prod_thr
    float acm = acoshf(thr_theta);
    const float sq_min = fminf(K * acm * acm, MAXSQ);

    const float4* E4 = (const float4*)emb;

    // D = sqdist(left, right) + GAMMA  (one-time shfl butterfly, warp-uniform)
    float4 lv = E4[(size_t)l * (DIM / 4) + lane];
    float4 rv = E4[(size_t)r * (DIM / 4) + lane];
    float pd = lv.x * rv.x + lv.y * rv.y + lv.z * rv.z + lv.w * rv.w;
    if (lane == 0) pd -= 2.0f * lv.x * rv.x;   // Minkowski: -x0*y0
    #pragma unroll
    for (int o = 16; o; o >>= 1) pd += __shfl_xor_sync(0xffffffffu, pd, o);
    float th = fmaxf(-pd * c, thr_theta);
    float ac = acoshf(th);
    const float D = fminf(K * ac * ac, MAXSQ) + GAMMA;

    // stage query into smem, dim0 negated so plain dot == Minkowski dot
    const int qrow = (side == 0) ? l : r;
    {
        float4 qv = E4[(size_t)qrow * (DIM / 4) + lane];
        if (lane == 0) qv.x = -qv.x;
        *(float4*)&s_q[wid][lane * 4] = qv;
    }

    // ---- tile loop: count clipped candidates, lane-per-candidate ----
    int  cnt  = 0;
    int  done = 0;
    int  tiles_run = 0;
    for (int tile = 0; tile < NT; ++tile) {
        const int base = tile * TILE;
        // cooperative tile load: 32 rows x 32 float4, 4 float4 per thread
        #pragma unroll
        for (int k = 0; k < 4; ++k) {
            int idx = t + k * 256;            // 0..1023
            int row = idx >> 5;
            int col = idx & 31;
            int cand = base + row;
            float4 v = make_float4(0.f, 0.f, 0.f, 0.f);
            if (cand < N_NODES) v = E4[(size_t)cand * (DIM / 4) + col];
            *(float4*)&s_cand[row][col * 4] = v;
        }
        __syncthreads();

        if (!done) {
            const int cand = base + lane;
            float p = 0.0f;
            const float4* cr = (const float4*)&s_cand[lane][0];
            const float4* qr = (const float4*)&s_q[wid][0];
            #pragma unroll
            for (int i = 0; i < DIM / 4; ++i) {
                float4 a = cr[i], b = qr[i];
                p += a.x * b.x + a.y * b.y + a.z * b.z + a.w * b.w;
            }
            unsigned m = __ballot_sync(0xffffffffu,
                                       (cand < N_NODES) && (p >= prod_thr));
            cnt += __popc(m);
            if (cnt >= K_NEG) done = 1;
        }
        ++tiles_run;
        if (__syncthreads_and(done)) break;   // also guards smem reuse
    }

    // ---- per-warp contribution ----
    float contrib;
    if (cnt >= K_NEG) {
        contrib = (float)K_NEG * fmaxf(D - sq_min, 0.0f);
    } else {
        // generic fallback: top-75 largest (prod, -idx), lexicographic order.
        const float* q = emb + (size_t)qrow * DIM;
        float prevP = INFINITY; int prevI = -1;
        float s = 0.0f;
        for (int pick = 0; pick < K_NEG; ++pick) {
            float bp = -INFINITY; int bi = 0x7fffffff;
            for (int j = lane; j < N_NODES; j += 32) {
                const float* e = emb + (size_t)j * DIM;
                float p = -q[0] * e[0];
                #pragma unroll 8
                for (int d = 1; d < DIM; ++d) p += q[d] * e[d];
                bool after = (p < prevP) || (p == prevP && j > prevI);
                if (after && (p > bp || (p == bp && j < bi))) { bp = p; bi = j; }
            }
            #pragma unroll
            for (int o = 16; o; o >>= 1) {
                float op = __shfl_xor_sync(0xffffffffu, bp, o);
                int   oi = __shfl_xor_sync(0xffffffffu, bi, o);
                if (op > bp || (op == bp && oi < bi)) { bp = op; bi = oi; }
            }
            prevP = bp; prevI = bi;
            float t2 = fmaxf(-bp * c, thr_theta);
            float a2 = acoshf(t2);
            float sq = fminf(K * a2 * a2, MAXSQ);
            s += fmaxf(D - sq, 0.0f);
        }
        contrib = s;
    }

    if (lane == 0) s_wsum[wid] = contrib;
    __syncthreads();

    // ---- block sum -> partial, last-block-done final reduction ----
    if (t == 0) {
        float bs = 0.0f;
        #pragma unroll
        for (int w = 0; w < WARPS_PER_BLOCK; ++w) bs += s_wsum[w];
        g_partial[bid] = bs;
        __threadfence();
        unsigned old = atomicInc(&g_ticket, NB - 1);  // wraps to 0 for replays
        s_islast = (old == NB - 1);
    }
    __syncthreads();

    if (s_islast) {
        __shared__ float sm[256];
        float s = 0.0f;
        for (int i = t; i < NB; i += 256) s += g_partial[i];
        sm[t] = s;
        __syncthreads();
        #pragma unroll
        for (int o = 128; o; o >>= 1) {
            if (t < o) sm[t] += sm[t + o];
            __syncthreads();
        }
        if (t == 0)
            out[0] = sm[0] / (2.0f * (float)K_NEG * (float)T_LINKS);
    }
}

extern "C" void kernel_launch(void* const* d_in, const int* in_sizes, int n_in,
                              void* d_out, int out_size) {
    const float* emb   = (const float*)d_in[0];
    const float* cptr  = (const float*)d_in[1];
    const void*  links = d_in[2];

    fused_kernel<<<NB, 256>>>(emb, cptr, links, (float*)d_out);
}

// round 5
// speedup vs baseline: 1.0662x; 1.0339x over previous
#include <cuda_runtime.h>
#include <math.h>

#define N_NODES 30000
#define DIM     128
#define T_LINKS 3000
#define K_NEG   75
#define NQ      (2 * T_LINKS)
#define EPSF    1e-7f
#define MAXSQ   50.0f
#define GAMMA   1.0f

#define WARPS_PER_BLOCK 8
#define NB (NQ / WARPS_PER_BLOCK)         // 750 blocks, 8 queries per block
#define TILE 32                            // candidates per smem tile
#define NT ((N_NODES + TILE - 1) / TILE)   // 938 tiles
#define ROWF 132                           // padded row stride (floats)

// ---------------- scratch (no device allocations allowed) ----------------
__device__ float        g_partial[NB];
__device__ unsigned int g_ticket = 0;

// One fused kernel. Math: sq(prod) = min(K*acosh(max(-prod*c,1+eps))^2, 50) is
// weakly monotone non-increasing in prod, so the 75 smallest distances are the
// 75 largest Minkowski prods. With emb ~ N(0,1), ~16000 of 30000 candidates
// clip to theta = 1+eps (the global minimum sq_min), so the 75 nearest all
// have sq = sq_min exactly and the row contribution is 75*relu(D - sq_min).
// We verify by counting clipped candidates with early exit (~160 scanned).
// Lane = (candidate, query) pair so each candidate smem read serves 8 queries.
// Generic lexicographic top-75 fallback guarantees correctness if any query
// ends with count < 75 (never triggers on this data).
__global__ void __launch_bounds__(256)
fused_kernel(const float* __restrict__ emb,
             const float* __restrict__ cptr,
             const void*  __restrict__ links,
             float* __restrict__ out) {
    __shared__ float s_cand[TILE][ROWF];          // 16896 B
    __shared__ float s_q[WARPS_PER_BLOCK][ROWF];  //  4224 B
    __shared__ int   s_qcnt[WARPS_PER_BLOCK];
    __shared__ float s_wsum[WARPS_PER_BLOCK];
    __shared__ int   s_islast;

    const int t    = threadIdx.x;
    const int wid  = t >> 5;
    const int lane = t & 31;
    const int bid  = blockIdx.x;

    // ---- link dtype detection (int64-LE with values<30000 => odd words 0) ----
    int loc = 0;
    {
        const int* w = (const int*)links;
        for (int i = t; i < T_LINKS; i += 256)
            if (w[2 * i + 1] != 0) loc = 1;
    }
    if (t < WARPS_PER_BLOCK) s_qcnt[t] = 0;
    const int is64 = !__syncthreads_or(loc);   // also publishes s_qcnt init

    // ---- per-warp query setup (warp w owns query w of this block) ----
    const int gwarp = bid * WARPS_PER_BLOCK + wid;
    const int li    = gwarp % T_LINKS;
    const int side  = gwarp / T_LINKS;         // 0 = left query, 1 = right

    int l, r;
    if (is64) {
        const long long* p = (const long long*)links;
        l = (int)p[2 * li]; r = (int)p[2 * li + 1];
    } else {
        const int* p = (const int*)links;
        l = p[2 * li]; r = p[2 * li + 1];
    }

    const float c  = cptr[0];
    const float K  = 1.0f / c;
    const float thr_theta = 1.0f + EPSF;       // rounds to 1+2^-23, same as jax fp32
    const float prod_thr  = -thr_theta * K;    // clipped  <=>  prod >= prod_thr
    float acm = acoshf(thr_theta);
    const float sq_min = fminf(K * acm * acm, MAXSQ);

    const float4* E4 = (const float4*)emb;

    // D = sqdist(left, right) + GAMMA (one-time butterfly, warp-uniform)
    float4 lv = E4[(size_t)l * (DIM / 4) + lane];
    float4 rv = E4[(size_t)r * (DIM / 4) + lane];
    float pd = lv.x * rv.x + lv.y * rv.y + lv.z * rv.z + lv.w * rv.w;
    if (lane == 0) pd -= 2.0f * lv.x * rv.x;   // Minkowski: -x0*y0
    #pragma unroll
    for (int o = 16; o; o >>= 1) pd += __shfl_xor_sync(0xffffffffu, pd, o);
    float th = fmaxf(-pd * c, thr_theta);
    float ac = acoshf(th);
    const float D = fminf(K * ac * ac, MAXSQ) + GAMMA;

    // stage query into smem, dim0 negated so plain dot == Minkowski dot
    const int qrow = (side == 0) ? l : r;
    {
        float4 qv = E4[(size_t)qrow * (DIM / 4) + lane];
        if (lane == 0) qv.x = -qv.x;
        *(float4*)&s_q[wid][lane * 4] = qv;
    }
    // (query smem publish covered by the first in-loop __syncthreads)

    // ---- lane roles for the scan ----
    const int my_cand_loc = (wid << 2) + (lane >> 3);   // 0..31 within tile
    const int my_query    = lane & 7;
    const float* cr = &s_cand[my_cand_loc][0];
    const float* qr = &s_q[my_query][0];

    // ---- tile loop ----
    for (int tile = 0; tile < NT; ++tile) {
        const int base = tile * TILE;
        // cooperative tile load: 32 rows x 32 float4, 4 float4 per thread
        #pragma unroll
        for (int k = 0; k < 4; ++k) {
            int idx = t + k * 256;             // 0..1023
            int row = idx >> 5;
            int col = idx & 31;
            int cand = base + row;
            float4 v = make_float4(0.f, 0.f, 0.f, 0.f);
            if (cand < N_NODES) v = E4[(size_t)cand * (DIM / 4) + col];
            *(float4*)&s_cand[row][col * 4] = v;
        }
        __syncthreads();                        // tile + queries + counters ready

        // each lane: full 128-dim dot for its (candidate, query) pair
        float acc = 0.0f;
        #pragma unroll
        for (int i = 0; i < DIM / 4; ++i) {
            float4 a = *(const float4*)&cr[4 * i];
            float4 b = *(const float4*)&qr[4 * i];
            acc += a.x * b.x + a.y * b.y + a.z * b.z + a.w * b.w;
        }
        const bool valid = (base + my_cand_loc) < N_NODES;
        unsigned bal = __ballot_sync(0xffffffffu, valid && (acc >= prod_thr));
        if (lane < WARPS_PER_BLOCK) {
            int cnt = __popc(bal & (0x01010101u << lane));
            if (cnt) atomicAdd(&s_qcnt[lane], cnt);
        }
        __syncthreads();                        // counters done; guards next STS

        // uniform early-exit check (broadcast smem reads)
        int4 c0 = *(const int4*)&s_qcnt[0];
        int4 c1 = *(const int4*)&s_qcnt[4];
        int mn = min(min(min(c0.x, c0.y), min(c0.z, c0.w)),
                     min(min(c1.x, c1.y), min(c1.z, c1.w)));
        if (mn >= K_NEG) break;
    }

    // ---- per-warp contribution (warp w -> query w) ----
    float contrib;
    if (s_qcnt[wid] >= K_NEG) {
        contrib = (float)K_NEG * fmaxf(D - sq_min, 0.0f);
    } else {
        // generic fallback: top-75 largest (prod, -idx), lexicographic order
        const float* q = emb + (size_t)qrow * DIM;
        float prevP = INFINITY; int prevI = -1;
        float s = 0.0f;
        for (int pick = 0; pick < K_NEG; ++pick) {
            float bp = -INFINITY; int bi = 0x7fffffff;
            for (int j = lane; j < N_NODES; j += 32) {
                const float* e = emb + (size_t)j * DIM;
                float p = -q[0] * e[0];
                #pragma unroll 8
                for (int d = 1; d < DIM; ++d) p += q[d] * e[d];
                bool after = (p < prevP) || (p == prevP && j > prevI);
                if (after && (p > bp || (p == bp && j < bi))) { bp = p; bi = j; }
            }
            #pragma unroll
            for (int o = 16; o; o >>= 1) {
                float op = __shfl_xor_sync(0xffffffffu, bp, o);
                int   oi = __shfl_xor_sync(0xffffffffu, bi, o);
                if (op > bp || (op == bp && oi < bi)) { bp = op; bi = oi; }
            }
            prevP = bp; prevI = bi;
            float t2 = fmaxf(-bp * c, thr_theta);
            float a2 = acoshf(t2);
            float sq = fminf(K * a2 * a2, MAXSQ);
            s += fmaxf(D - sq, 0.0f);
        }
        contrib = s;
    }

    if (lane == 0) s_wsum[wid] = contrib;
    __syncthreads();

    // ---- block sum -> partial, last-block-done final reduction ----
    if (t == 0) {
        float bs = 0.0f;
        #pragma unroll
        for (int w = 0; w < WARPS_PER_BLOCK; ++w) bs += s_wsum[w];
        g_partial[bid] = bs;
        __threadfence();
        unsigned old = atomicInc(&g_ticket, NB - 1);  // wraps to 0 for replays
        s_islast = (old == NB - 1);
    }
    __syncthreads();

    if (s_islast) {
        __shared__ float sm[256];
        float s = 0.0f;
        for (int i = t; i < NB; i += 256) s += g_partial[i];
        sm[t] = s;
        __syncthreads();
        #pragma unroll
        for (int o = 128; o; o >>= 1) {
            if (t < o) sm[t] += sm[t + o];
            __syncthreads();
        }
        if (t == 0)
            out[0] = sm[0] / (2.0f * (float)K_NEG * (float)T_LINKS);
    }
}

extern "C" void kernel_launch(void* const* d_in, const int* in_sizes, int n_in,
                              void* d_out, int out_size) {
    const float* emb   = (const float*)d_in[0];
    const float* cptr  = (const float*)d_in[1];
    const void*  links = d_in[2];

    fused_kernel<<<NB, 256>>>(emb, cptr, links, (float*)d_out);
}